// round 13
// baseline (speedup 1.0000x reference)
#include <cuda_runtime.h>
#include <cuda_fp16.h>
#include <cstdint>
#include <math.h>

// ---------------- problem constants ----------------
constexpr int T_TOK  = 8192;    // B*S
constexpr int D_MODEL = 1024;
constexpr int N_EXP  = 8;
constexpr int DFF    = 4096;
constexpr int CAP    = 1280;    // ceil(1.25*8192/8)

// ---------------- scratch (__device__ globals; alloc-free rule) ----------------
__device__ float  g_prob[T_TOK];
__device__ int    g_expert[T_TOK];
__device__ int    g_pos[T_TOK];
__device__ int    g_cnt[N_EXP];
__device__ int    g_slot2tok[N_EXP * CAP];
__device__ float  g_slot_prob[N_EXP * CAP];
__device__ __half g_disp[(size_t)N_EXP*CAP*D_MODEL];
__device__ __half g_w1[(size_t)N_EXP*DFF*D_MODEL];   // [e][dff][d]  K-major
__device__ __half g_w2[(size_t)N_EXP*D_MODEL*DFF];   // [e][d][dff]  K-major
__device__ __half g_h[(size_t)N_EXP*CAP*DFF];

// ---------------- helpers ----------------
static __device__ __forceinline__ uint32_t smem_u32(const void* p){
    uint32_t a;
    asm("{ .reg .u64 t; cvta.to.shared.u64 t, %1; cvt.u32.u64 %0, t; }" : "=r"(a) : "l"(p));
    return a;
}
static __device__ __forceinline__ void cp_async16(uint32_t s, const void* g){
    asm volatile("cp.async.cg.shared.global [%0], [%1], 16;" :: "r"(s), "l"(g) : "memory");
}
static __device__ __forceinline__ void cp_commit(){
    asm volatile("cp.async.commit_group;" ::: "memory");
}
template<int N>
static __device__ __forceinline__ void cp_wait(){
    asm volatile("cp.async.wait_group %0;" :: "n"(N) : "memory");
}
static __device__ __forceinline__ void ldmx4(uint32_t* r, uint32_t addr){
    asm volatile("ldmatrix.sync.aligned.m8n8.x4.shared.b16 {%0,%1,%2,%3}, [%4];"
                 : "=r"(r[0]), "=r"(r[1]), "=r"(r[2]), "=r"(r[3]) : "r"(addr));
}
static __device__ __forceinline__ void ldmx2(uint32_t* r, uint32_t addr){
    asm volatile("ldmatrix.sync.aligned.m8n8.x2.shared.b16 {%0,%1}, [%2];"
                 : "=r"(r[0]), "=r"(r[1]) : "r"(addr));
}
// fp16 operands, fp32 accumulator
static __device__ __forceinline__ void mma_f32(float* c, const uint32_t* a, const uint32_t* b){
    asm volatile(
        "mma.sync.aligned.m16n8k16.row.col.f32.f16.f16.f32 "
        "{%0,%1,%2,%3}, {%4,%5,%6,%7}, {%8,%9}, {%0,%1,%2,%3};"
        : "+f"(c[0]), "+f"(c[1]), "+f"(c[2]), "+f"(c[3])
        : "r"(a[0]), "r"(a[1]), "r"(a[2]), "r"(a[3]), "r"(b[0]), "r"(b[1]));
}

// ---------------- 1) gate: fp64-accum logits, softmax top-1 ----------------
__global__ void moe_gate(const float* __restrict__ tokens, const float* __restrict__ gw){
    __shared__ float s_gw[N_EXP * D_MODEL];  // 32 KB
    for (int i = threadIdx.x; i < N_EXP * D_MODEL; i += blockDim.x) s_gw[i] = gw[i];
    __syncthreads();
    int lane  = threadIdx.x & 31;
    int warp  = (blockIdx.x * blockDim.x + threadIdx.x) >> 5;
    int nwarp = (gridDim.x * blockDim.x) >> 5;
    for (int t = warp; t < T_TOK; t += nwarp){
        const float* tok = tokens + (size_t)t * D_MODEL;
        double acc[N_EXP];
        #pragma unroll
        for (int e = 0; e < N_EXP; e++) acc[e] = 0.0;
        for (int d = lane; d < D_MODEL; d += 32){
            double x = (double)tok[d];
            #pragma unroll
            for (int e = 0; e < N_EXP; e++) acc[e] += x * (double)s_gw[e * D_MODEL + d];
        }
        #pragma unroll
        for (int e = 0; e < N_EXP; e++){
            #pragma unroll
            for (int o = 16; o > 0; o >>= 1)
                acc[e] += __shfl_down_sync(0xffffffffu, acc[e], o);
        }
        if (lane == 0){
            int best = 0; double bv = acc[0];
            #pragma unroll
            for (int e = 1; e < N_EXP; e++) if (acc[e] > bv){ bv = acc[e]; best = e; }
            double s = 0.0;
            #pragma unroll
            for (int e = 0; e < N_EXP; e++) s += exp(acc[e] - bv);
            g_prob[t]   = (float)(1.0 / s);
            g_expert[t] = best;
        }
    }
}

// ---------------- 2) order-preserving per-expert rank scan + slot init ----------------
__global__ void moe_scan(){
    __shared__ int s_base[N_EXP];
    __shared__ int s_wcnt[N_EXP][32];
    int tid = threadIdx.x, lane = tid & 31, w = tid >> 5;
    for (int i = tid; i < N_EXP * CAP; i += 1024) g_slot2tok[i] = -1;
    if (tid < N_EXP) s_base[tid] = 0;
    for (int chunk = 0; chunk < T_TOK / 1024; chunk++){
        if (tid < N_EXP * 32) ((int*)s_wcnt)[tid] = 0;
        __syncthreads();
        int t = chunk * 1024 + tid;
        int e = g_expert[t];
        unsigned m = __match_any_sync(0xffffffffu, e);
        int rw = __popc(m & ((1u << lane) - 1u));
        if (rw == 0) s_wcnt[e][w] = __popc(m);
        __syncthreads();
        int base = s_base[e];
        for (int ww = 0; ww < w; ww++) base += s_wcnt[e][ww];
        int rank = base + rw;
        g_pos[t] = (rank < CAP) ? rank : -1;
        __syncthreads();
        if (tid < N_EXP){
            int s = 0;
            #pragma unroll
            for (int ww = 0; ww < 32; ww++) s += s_wcnt[tid][ww];
            s_base[tid] += s;
        }
        __syncthreads();
    }
    if (tid < N_EXP) g_cnt[tid] = (s_base[tid] < CAP) ? s_base[tid] : CAP;
}

// ---------------- 3) gather tokens -> dispatch (fp16) + slot maps + dropped-zero ------
__global__ void moe_gather(const float* __restrict__ tokens, float* __restrict__ out){
    int t = blockIdx.x;
    int pos = g_pos[t];
    if (pos < 0){
        float4* o = (float4*)(out + (size_t)t * D_MODEL);
        for (int i = threadIdx.x; i < D_MODEL / 4; i += blockDim.x)
            o[i] = make_float4(0.f, 0.f, 0.f, 0.f);
        return;
    }
    int e = g_expert[t];
    if (threadIdx.x == 0){
        g_slot2tok[e * CAP + pos]  = t;
        g_slot_prob[e * CAP + pos] = g_prob[t];
    }
    size_t dst = ((size_t)e * CAP + pos) * D_MODEL;
    const float4* src = (const float4*)(tokens + (size_t)t * D_MODEL);
    uint2* dh = (uint2*)(g_disp + dst);
    for (int i = threadIdx.x; i < D_MODEL / 4; i += blockDim.x){
        float4 v = src[i];
        __half2 h0 = __floats2half2_rn(v.x, v.y);
        __half2 h1 = __floats2half2_rn(v.z, v.w);
        uint2 H;
        H.x = *reinterpret_cast<unsigned*>(&h0);
        H.y = *reinterpret_cast<unsigned*>(&h1);
        dh[i] = H;
    }
}

// ---------------- 4) weight transpose (to K-major fp16) ----------------
template<bool W1>
__global__ void moe_tw(const float* __restrict__ w){
    constexpr int R = W1 ? D_MODEL : DFF;   // rows of w  (= K of gemm)
    constexpr int C = W1 ? DFF : D_MODEL;   // cols of w  (= N of gemm)
    __half* oh = W1 ? g_w1 : g_w2;
    __shared__ float tile[32][33];
    int e = blockIdx.z;
    int c0 = blockIdx.x * 32, r0 = blockIdx.y * 32;
    const float* wp = w + (size_t)e * R * C;
    int x = threadIdx.x, y0 = threadIdx.y;    // blockDim (32, 8)
    #pragma unroll
    for (int yy = 0; yy < 32; yy += 8)
        tile[y0 + yy][x] = wp[(size_t)(r0 + y0 + yy) * C + c0 + x];
    __syncthreads();
    __half* poh = oh + (size_t)e * R * C;
    #pragma unroll
    for (int yy = 0; yy < 32; yy += 8){
        float v = tile[x][y0 + yy];
        size_t o = (size_t)(c0 + y0 + yy) * R + r0 + x;
        poh[o] = __float2half_rn(v);
    }
}

// ---------------- 5) HMMA fp16 GEMM: BM=128 BN=128 BK=64, 3-stage, 2 CTA/SM -----------
constexpr int BM = 128, BN = 128, BK = 64;
constexpr int ROW_B   = 144;                     // 128B data + 16B pad (conflict-free)
constexpr int OFF_A   = 0;
constexpr int OFF_B   = 128 * ROW_B;
constexpr int STAGE_B = 256 * ROW_B;             // 36864
constexpr int NSTAGE  = 3;
constexpr int GEMM_SMEM = NSTAGE * STAGE_B;      // 110592 (x2 CTA = 216 KB/SM)

template<bool G1>
__global__ void __launch_bounds__(256, 2) moe_gemm(const float* __restrict__ bias,
                                                   float* __restrict__ out){
    constexpr int KTOT = G1 ? D_MODEL : DFF;
    constexpr int NTOT = G1 ? DFF : D_MODEL;
    const __half* A = G1 ? g_disp : g_h;
    const __half* B = G1 ? g_w1 : g_w2;

    int e = blockIdx.z, m0 = blockIdx.y * BM, n0 = blockIdx.x * BN;
    int cnt = g_cnt[e];
    if (m0 >= cnt) return;          // expert has no tokens in this m-tile

    extern __shared__ char smem[];
    uint32_t sb = smem_u32(smem);

    int tid  = threadIdx.x;
    int lane = tid & 31;
    int wid  = tid >> 5;
    int warpM = wid & 1;            // 2 x 4 warp grid; warp tile 64x32
    int warpN = wid >> 1;

    const __half* baseA = A + ((size_t)e * CAP  + m0) * KTOT;
    const __half* baseB = B + ((size_t)e * NTOT + n0) * KTOT;

    // per-thread cp.async slots: idx = tid + i*256 (i<8); row = idx>>3 (0..255), ch = idx&7
    const __half* gptr[8];
    uint32_t sptr[8];
    #pragma unroll
    for (int i = 0; i < 8; i++){
        int idx = tid + i * 256;
        int row = idx >> 3, ch = idx & 7;
        const __half* gb; uint32_t so;
        if (row < 128) { gb = baseA + (size_t)row * KTOT;        so = OFF_A + row * ROW_B; }
        else           { gb = baseB + (size_t)(row-128) * KTOT;  so = OFF_B + (row-128) * ROW_B; }
        gptr[i] = gb + ch * 8;
        sptr[i] = sb + so + ch * 16;
    }
    auto load_stage = [&](int kc, int stage){
        size_t koff = (size_t)kc * BK;
        uint32_t soff = stage * STAGE_B;
        #pragma unroll
        for (int i = 0; i < 8; i++)
            cp_async16(sptr[i] + soff, gptr[i] + koff);
    };

    constexpr int NK = KTOT / BK;
    #pragma unroll
    for (int s = 0; s < NSTAGE - 1; s++){ load_stage(s, s); cp_commit(); }

    float accF[4][4][4];
    #pragma unroll
    for (int mt = 0; mt < 4; mt++)
        #pragma unroll
        for (int nt = 0; nt < 4; nt++)
            #pragma unroll
            for (int c = 0; c < 4; c++) accF[mt][nt][c] = 0.f;

    uint32_t aoff = (uint32_t)((warpM * 64 + (lane & 7) + ((lane >> 3) & 1) * 8) * ROW_B
                    + ((lane >> 4) & 1) * 16);
    uint32_t boff = (uint32_t)((warpN * 32 + (lane & 7)) * ROW_B + ((lane >> 3) & 1) * 16);

    int cur = 0, lds = NSTAGE - 1;
    #pragma unroll 1
    for (int kc = 0; kc < NK; kc++){
        cp_wait<NSTAGE - 2>();
        __syncthreads();
        int nx = kc + NSTAGE - 1;
        if (nx < NK) load_stage(nx, lds);
        cp_commit();

        uint32_t st = sb + cur * STAGE_B;
        uint32_t aH = st + OFF_A + aoff;
        uint32_t bH = st + OFF_B + boff;
        #pragma unroll
        for (int ks = 0; ks < 4; ks++){          // 4 x k16 per 64-deep chunk
            uint32_t bh[4][2];
            #pragma unroll
            for (int nt = 0; nt < 4; nt++)
                ldmx2(bh[nt], bH + nt * 8 * ROW_B + ks * 32);
            #pragma unroll
            for (int mt = 0; mt < 4; mt++){
                uint32_t ah[4];
                ldmx4(ah, aH + mt * 16 * ROW_B + ks * 32);
                #pragma unroll
                for (int nt = 0; nt < 4; nt++)
                    mma_f32(accF[mt][nt], ah, bh[nt]);
            }
        }
        cur = (cur == NSTAGE - 1) ? 0 : cur + 1;
        lds = (lds == NSTAGE - 1) ? 0 : lds + 1;
    }

    // epilogue
    int rloc  = warpM * 64 + (lane >> 2);
    int cbase = n0 + warpN * 32 + 2 * (lane & 3);
    const float* bptr = bias + (size_t)e * NTOT;
    #pragma unroll
    for (int mt = 0; mt < 4; mt++){
        #pragma unroll
        for (int h = 0; h < 2; h++){
            int slot = m0 + rloc + mt * 16 + h * 8;
            int t = 0; float p = 0.f; float* op = nullptr;
            if constexpr (!G1){
                t = g_slot2tok[e * CAP + slot];
                if (t < 0) continue;
                p = g_slot_prob[e * CAP + slot];
                op = out + (size_t)t * D_MODEL;
            }
            size_t row = (size_t)e * CAP + slot;
            #pragma unroll
            for (int nt = 0; nt < 4; nt++){
                int n = cbase + nt * 8;
                float v0 = accF[mt][nt][h*2+0] + __ldg(bptr + n);
                float v1 = accF[mt][nt][h*2+1] + __ldg(bptr + n + 1);
                if constexpr (G1){
                    v0 = fmaxf(v0, 0.f); v1 = fmaxf(v1, 0.f);
                    __half2 hv = __floats2half2_rn(v0, v1);
                    *(unsigned*)(g_h + row * DFF + n) = *reinterpret_cast<unsigned*>(&hv);
                } else {
                    float2 v = make_float2(v0 * p, v1 * p);
                    *(float2*)(op + n) = v;
                }
            }
        }
    }
}

// ---------------- launch ----------------
extern "C" void kernel_launch(void* const* d_in, const int* in_sizes, int n_in,
                              void* d_out, int out_size){
    const float* inputs = (const float*)d_in[0];
    const float* gate_w = (const float*)d_in[1];
    const float* w1     = (const float*)d_in[2];
    const float* b1     = (const float*)d_in[3];
    const float* w2     = (const float*)d_in[4];
    const float* b2     = (const float*)d_in[5];
    float* out = (float*)d_out;

    cudaFuncSetAttribute(moe_gemm<true>,  cudaFuncAttributeMaxDynamicSharedMemorySize, GEMM_SMEM);
    cudaFuncSetAttribute(moe_gemm<false>, cudaFuncAttributeMaxDynamicSharedMemorySize, GEMM_SMEM);

    moe_gate<<<128, 256>>>(inputs, gate_w);
    moe_scan<<<1, 1024>>>();
    moe_gather<<<T_TOK, 128>>>(inputs, out);
    moe_tw<true ><<<dim3(DFF / 32,     D_MODEL / 32, N_EXP), dim3(32, 8)>>>(w1);
    moe_tw<false><<<dim3(D_MODEL / 32, DFF / 32,     N_EXP), dim3(32, 8)>>>(w2);
    moe_gemm<true ><<<dim3(DFF / BN,     CAP / BM, N_EXP), 256, GEMM_SMEM>>>(b1, nullptr);
    moe_gemm<false><<<dim3(D_MODEL / BN, CAP / BM, N_EXP), 256, GEMM_SMEM>>>(b2, out);
}

// round 14
// speedup vs baseline: 1.4611x; 1.4611x over previous
#include <cuda_runtime.h>
#include <cuda_fp16.h>
#include <cstdint>
#include <math.h>

// ---------------- problem constants ----------------
constexpr int T_TOK  = 8192;    // B*S
constexpr int D_MODEL = 1024;
constexpr int N_EXP  = 8;
constexpr int DFF    = 4096;
constexpr int CAP    = 1280;    // ceil(1.25*8192/8)

// ---------------- scratch (__device__ globals; alloc-free rule) ----------------
__device__ float  g_prob[T_TOK];
__device__ int    g_expert[T_TOK];
__device__ int    g_pos[T_TOK];
__device__ int    g_cnt[N_EXP];
__device__ int    g_tile[2];                 // persistent-GEMM work counters
__device__ int    g_slot2tok[N_EXP * CAP];
__device__ float  g_slot_prob[N_EXP * CAP];
__device__ __half g_disp[(size_t)N_EXP*CAP*D_MODEL];
__device__ __half g_w1[(size_t)N_EXP*DFF*D_MODEL];   // [e][dff][d]  K-major
__device__ __half g_w2[(size_t)N_EXP*D_MODEL*DFF];   // [e][d][dff]  K-major
__device__ __half g_h[(size_t)N_EXP*CAP*DFF];

// ---------------- helpers ----------------
static __device__ __forceinline__ uint32_t smem_u32(const void* p){
    uint32_t a;
    asm("{ .reg .u64 t; cvta.to.shared.u64 t, %1; cvt.u32.u64 %0, t; }" : "=r"(a) : "l"(p));
    return a;
}
static __device__ __forceinline__ void cp_async16(uint32_t s, const void* g){
    asm volatile("cp.async.cg.shared.global [%0], [%1], 16;" :: "r"(s), "l"(g) : "memory");
}
static __device__ __forceinline__ void cp_commit(){
    asm volatile("cp.async.commit_group;" ::: "memory");
}
template<int N>
static __device__ __forceinline__ void cp_wait(){
    asm volatile("cp.async.wait_group %0;" :: "n"(N) : "memory");
}
static __device__ __forceinline__ void ldmx4(uint32_t* r, uint32_t addr){
    asm volatile("ldmatrix.sync.aligned.m8n8.x4.shared.b16 {%0,%1,%2,%3}, [%4];"
                 : "=r"(r[0]), "=r"(r[1]), "=r"(r[2]), "=r"(r[3]) : "r"(addr));
}
static __device__ __forceinline__ void ldmx2(uint32_t* r, uint32_t addr){
    asm volatile("ldmatrix.sync.aligned.m8n8.x2.shared.b16 {%0,%1}, [%2];"
                 : "=r"(r[0]), "=r"(r[1]) : "r"(addr));
}
// fp16 operands, fp32 accumulator
static __device__ __forceinline__ void mma_f32(float* c, const uint32_t* a, const uint32_t* b){
    asm volatile(
        "mma.sync.aligned.m16n8k16.row.col.f32.f16.f16.f32 "
        "{%0,%1,%2,%3}, {%4,%5,%6,%7}, {%8,%9}, {%0,%1,%2,%3};"
        : "+f"(c[0]), "+f"(c[1]), "+f"(c[2]), "+f"(c[3])
        : "r"(a[0]), "r"(a[1]), "r"(a[2]), "r"(a[3]), "r"(b[0]), "r"(b[1]));
}

// ---------------- 1) gate: fp64-accum logits, softmax top-1 ----------------
__global__ void moe_gate(const float* __restrict__ tokens, const float* __restrict__ gw){
    __shared__ float s_gw[N_EXP * D_MODEL];  // 32 KB
    for (int i = threadIdx.x; i < N_EXP * D_MODEL; i += blockDim.x) s_gw[i] = gw[i];
    __syncthreads();
    int lane  = threadIdx.x & 31;
    int warp  = (blockIdx.x * blockDim.x + threadIdx.x) >> 5;
    int nwarp = (gridDim.x * blockDim.x) >> 5;
    for (int t = warp; t < T_TOK; t += nwarp){
        const float* tok = tokens + (size_t)t * D_MODEL;
        double acc[N_EXP];
        #pragma unroll
        for (int e = 0; e < N_EXP; e++) acc[e] = 0.0;
        for (int d = lane; d < D_MODEL; d += 32){
            double x = (double)tok[d];
            #pragma unroll
            for (int e = 0; e < N_EXP; e++) acc[e] += x * (double)s_gw[e * D_MODEL + d];
        }
        #pragma unroll
        for (int e = 0; e < N_EXP; e++){
            #pragma unroll
            for (int o = 16; o > 0; o >>= 1)
                acc[e] += __shfl_down_sync(0xffffffffu, acc[e], o);
        }
        if (lane == 0){
            int best = 0; double bv = acc[0];
            #pragma unroll
            for (int e = 1; e < N_EXP; e++) if (acc[e] > bv){ bv = acc[e]; best = e; }
            double s = 0.0;
            #pragma unroll
            for (int e = 0; e < N_EXP; e++) s += exp(acc[e] - bv);
            g_prob[t]   = (float)(1.0 / s);
            g_expert[t] = best;
        }
    }
}

// ---------------- 2) order-preserving per-expert rank scan + slot/counter init --------
__global__ void moe_scan(){
    __shared__ int s_base[N_EXP];
    __shared__ int s_wcnt[N_EXP][32];
    int tid = threadIdx.x, lane = tid & 31, w = tid >> 5;
    for (int i = tid; i < N_EXP * CAP; i += 1024) g_slot2tok[i] = -1;
    if (tid < 2) g_tile[tid] = 0;                    // reset persistent-GEMM counters
    if (tid < N_EXP) s_base[tid] = 0;
    for (int chunk = 0; chunk < T_TOK / 1024; chunk++){
        if (tid < N_EXP * 32) ((int*)s_wcnt)[tid] = 0;
        __syncthreads();
        int t = chunk * 1024 + tid;
        int e = g_expert[t];
        unsigned m = __match_any_sync(0xffffffffu, e);
        int rw = __popc(m & ((1u << lane) - 1u));
        if (rw == 0) s_wcnt[e][w] = __popc(m);
        __syncthreads();
        int base = s_base[e];
        for (int ww = 0; ww < w; ww++) base += s_wcnt[e][ww];
        int rank = base + rw;
        g_pos[t] = (rank < CAP) ? rank : -1;
        __syncthreads();
        if (tid < N_EXP){
            int s = 0;
            #pragma unroll
            for (int ww = 0; ww < 32; ww++) s += s_wcnt[tid][ww];
            s_base[tid] += s;
        }
        __syncthreads();
    }
    if (tid < N_EXP) g_cnt[tid] = (s_base[tid] < CAP) ? s_base[tid] : CAP;
}

// ---------------- 3) gather tokens -> dispatch (fp16) + slot maps + dropped-zero ------
__global__ void moe_gather(const float* __restrict__ tokens, float* __restrict__ out){
    int t = blockIdx.x;
    int pos = g_pos[t];
    if (pos < 0){
        float4* o = (float4*)(out + (size_t)t * D_MODEL);
        for (int i = threadIdx.x; i < D_MODEL / 4; i += blockDim.x)
            o[i] = make_float4(0.f, 0.f, 0.f, 0.f);
        return;
    }
    int e = g_expert[t];
    if (threadIdx.x == 0){
        g_slot2tok[e * CAP + pos]  = t;
        g_slot_prob[e * CAP + pos] = g_prob[t];
    }
    size_t dst = ((size_t)e * CAP + pos) * D_MODEL;
    const float4* src = (const float4*)(tokens + (size_t)t * D_MODEL);
    uint2* dh = (uint2*)(g_disp + dst);
    for (int i = threadIdx.x; i < D_MODEL / 4; i += blockDim.x){
        float4 v = src[i];
        __half2 h0 = __floats2half2_rn(v.x, v.y);
        __half2 h1 = __floats2half2_rn(v.z, v.w);
        uint2 H;
        H.x = *reinterpret_cast<unsigned*>(&h0);
        H.y = *reinterpret_cast<unsigned*>(&h1);
        dh[i] = H;
    }
}

// ---------------- 4) weight transpose (to K-major fp16) ----------------
template<bool W1>
__global__ void moe_tw(const float* __restrict__ w){
    constexpr int R = W1 ? D_MODEL : DFF;   // rows of w  (= K of gemm)
    constexpr int C = W1 ? DFF : D_MODEL;   // cols of w  (= N of gemm)
    __half* oh = W1 ? g_w1 : g_w2;
    __shared__ float tile[32][33];
    int e = blockIdx.z;
    int c0 = blockIdx.x * 32, r0 = blockIdx.y * 32;
    const float* wp = w + (size_t)e * R * C;
    int x = threadIdx.x, y0 = threadIdx.y;    // blockDim (32, 8)
    #pragma unroll
    for (int yy = 0; yy < 32; yy += 8)
        tile[y0 + yy][x] = wp[(size_t)(r0 + y0 + yy) * C + c0 + x];
    __syncthreads();
    __half* poh = oh + (size_t)e * R * C;
    #pragma unroll
    for (int yy = 0; yy < 32; yy += 8){
        float v = tile[x][y0 + yy];
        size_t o = (size_t)(c0 + y0 + yy) * R + r0 + x;
        poh[o] = __float2half_rn(v);
    }
}

// ---------------- 5) persistent HMMA fp16 GEMM: BM=128 BN=128 BK=32, 4-stage ----------
constexpr int BM = 128, BN = 128, BK = 32;
constexpr int ROW_B   = 80;                      // padded row stride (64B data + 16B pad)
constexpr int OFF_A   = 0;
constexpr int OFF_B   = 128 * ROW_B;
constexpr int STAGE_B = 256 * ROW_B;             // 20480
constexpr int NSTAGE  = 4;
constexpr int GEMM_SMEM = NSTAGE * STAGE_B;      // 81920
constexpr int GRID_PERSIST = 296;                // 2 CTAs/SM x 148 SMs

template<bool G1>
__global__ void __launch_bounds__(256, 2) moe_gemm(const float* __restrict__ bias,
                                                   float* __restrict__ out){
    constexpr int KTOT = G1 ? D_MODEL : DFF;
    constexpr int NTOT = G1 ? DFF : D_MODEL;
    constexpr int MT   = CAP / BM;               // 10
    constexpr int NT   = NTOT / BN;              // 32 (G1) / 8 (G2)
    constexpr int TOTAL = N_EXP * MT * NT;
    const __half* A = G1 ? g_disp : g_h;
    const __half* B = G1 ? g_w1 : g_w2;

    extern __shared__ char smem[];
    uint32_t sb = smem_u32(smem);
    __shared__ int s_tile;

    int tid  = threadIdx.x;
    int lane = tid & 31;
    int wid  = tid >> 5;
    int warpM = wid & 1;            // 2 x 4 warp grid; warp tile 64x32
    int warpN = wid >> 1;

    // static per-thread smem slots: idx = tid + i*256 (i<4); row = idx>>2, ch = idx&3
    uint32_t sptr[4];
    int srow[4], sch[4];
    #pragma unroll
    for (int i = 0; i < 4; i++){
        int idx = tid + i * 256;
        srow[i] = idx >> 2; sch[i] = idx & 3;
        uint32_t so = (srow[i] < 128) ? (OFF_A + srow[i] * ROW_B)
                                      : (OFF_B + (srow[i] - 128) * ROW_B);
        sptr[i] = sb + so + sch[i] * 16;
    }
    uint32_t aoff = (uint32_t)((warpM * 64 + (lane & 7) + ((lane >> 3) & 1) * 8) * ROW_B
                    + ((lane >> 4) & 1) * 16);
    uint32_t boff = (uint32_t)((warpN * 32 + (lane & 7)) * ROW_B + ((lane >> 3) & 1) * 16);

    for (;;){
        if (tid == 0) s_tile = atomicAdd(&g_tile[G1 ? 0 : 1], 1);
        __syncthreads();                 // broadcast tile; also fences smem reuse
        int tile = s_tile;
        if (tile >= TOTAL) break;

        int e  = tile / (MT * NT);
        int r  = tile - e * (MT * NT);
        int n0 = (r / MT) * BN;          // m fastest: concurrent CTAs share B tile
        int m0 = (r % MT) * BM;
        if (m0 >= g_cnt[e]) continue;    // empty m-tile: steal next

        const __half* baseA = A + ((size_t)e * CAP  + m0) * KTOT;
        const __half* baseB = B + ((size_t)e * NTOT + n0) * KTOT;
        const __half* gptr[4];
        #pragma unroll
        for (int i = 0; i < 4; i++){
            const __half* gb = (srow[i] < 128) ? (baseA + (size_t)srow[i] * KTOT)
                                               : (baseB + (size_t)(srow[i] - 128) * KTOT);
            gptr[i] = gb + sch[i] * 8;
        }
        auto load_stage = [&](int kc, int stage){
            size_t koff = (size_t)kc * BK;
            uint32_t soff = stage * STAGE_B;
            #pragma unroll
            for (int i = 0; i < 4; i++)
                cp_async16(sptr[i] + soff, gptr[i] + koff);
        };

        constexpr int NK = KTOT / BK;
        #pragma unroll
        for (int s = 0; s < NSTAGE - 1; s++){ load_stage(s, s); cp_commit(); }

        float accF[4][4][4];
        #pragma unroll
        for (int mt = 0; mt < 4; mt++)
            #pragma unroll
            for (int nt = 0; nt < 4; nt++)
                #pragma unroll
                for (int c = 0; c < 4; c++) accF[mt][nt][c] = 0.f;

        int cur = 0, lds = NSTAGE - 1;
        #pragma unroll 1
        for (int kc = 0; kc < NK; kc++){
            cp_wait<NSTAGE - 2>();
            __syncthreads();
            int nx = kc + NSTAGE - 1;
            if (nx < NK) load_stage(nx, lds);
            cp_commit();

            uint32_t st = sb + cur * STAGE_B;
            uint32_t aH = st + OFF_A + aoff;
            uint32_t bH = st + OFF_B + boff;
            #pragma unroll
            for (int ks = 0; ks < 2; ks++){
                uint32_t bh[4][2];
                #pragma unroll
                for (int nt = 0; nt < 4; nt++)
                    ldmx2(bh[nt], bH + nt * 8 * ROW_B + ks * 32);
                #pragma unroll
                for (int mt = 0; mt < 4; mt++){
                    uint32_t ah[4];
                    ldmx4(ah, aH + mt * 16 * ROW_B + ks * 32);
                    #pragma unroll
                    for (int nt = 0; nt < 4; nt++)
                        mma_f32(accF[mt][nt], ah, bh[nt]);
                }
            }
            cur = (cur == NSTAGE - 1) ? 0 : cur + 1;
            lds = (lds == NSTAGE - 1) ? 0 : lds + 1;
        }

        // epilogue
        int rloc  = warpM * 64 + (lane >> 2);
        int cbase = n0 + warpN * 32 + 2 * (lane & 3);
        const float* bptr = bias + (size_t)e * NTOT;
        #pragma unroll
        for (int mt = 0; mt < 4; mt++){
            #pragma unroll
            for (int h = 0; h < 2; h++){
                int slot = m0 + rloc + mt * 16 + h * 8;
                int t = 0; float p = 0.f; float* op = nullptr;
                if constexpr (!G1){
                    t = g_slot2tok[e * CAP + slot];
                    if (t < 0) continue;
                    p = g_slot_prob[e * CAP + slot];
                    op = out + (size_t)t * D_MODEL;
                }
                size_t row = (size_t)e * CAP + slot;
                #pragma unroll
                for (int nt = 0; nt < 4; nt++){
                    int n = cbase + nt * 8;
                    float v0 = accF[mt][nt][h*2+0] + __ldg(bptr + n);
                    float v1 = accF[mt][nt][h*2+1] + __ldg(bptr + n + 1);
                    if constexpr (G1){
                        v0 = fmaxf(v0, 0.f); v1 = fmaxf(v1, 0.f);
                        __half2 hv = __floats2half2_rn(v0, v1);
                        *(unsigned*)(g_h + row * DFF + n) = *reinterpret_cast<unsigned*>(&hv);
                    } else {
                        float2 v = make_float2(v0 * p, v1 * p);
                        *(float2*)(op + n) = v;
                    }
                }
            }
        }
    }
}

// ---------------- launch ----------------
extern "C" void kernel_launch(void* const* d_in, const int* in_sizes, int n_in,
                              void* d_out, int out_size){
    const float* inputs = (const float*)d_in[0];
    const float* gate_w = (const float*)d_in[1];
    const float* w1     = (const float*)d_in[2];
    const float* b1     = (const float*)d_in[3];
    const float* w2     = (const float*)d_in[4];
    const float* b2     = (const float*)d_in[5];
    float* out = (float*)d_out;

    cudaFuncSetAttribute(moe_gemm<true>,  cudaFuncAttributeMaxDynamicSharedMemorySize, GEMM_SMEM);
    cudaFuncSetAttribute(moe_gemm<false>, cudaFuncAttributeMaxDynamicSharedMemorySize, GEMM_SMEM);

    moe_gate<<<128, 256>>>(inputs, gate_w);                                          // 1
    moe_scan<<<1, 1024>>>();                                                         // 2
    moe_gather<<<T_TOK, 128>>>(inputs, out);                                         // 3
    moe_tw<true ><<<dim3(DFF / 32,     D_MODEL / 32, N_EXP), dim3(32, 8)>>>(w1);     // 4
    moe_tw<false><<<dim3(D_MODEL / 32, DFF / 32,     N_EXP), dim3(32, 8)>>>(w2);     // 5
    moe_gemm<true ><<<GRID_PERSIST, 256, GEMM_SMEM>>>(b1, nullptr);                  // 6 (ncu -s 5)
    moe_gemm<false><<<GRID_PERSIST, 256, GEMM_SMEM>>>(b2, out);                      // 7
}

// round 15
// speedup vs baseline: 1.6103x; 1.1021x over previous
#include <cuda_runtime.h>
#include <cuda_fp16.h>
#include <cstdint>
#include <math.h>

// ---------------- problem constants ----------------
constexpr int T_TOK  = 8192;    // B*S
constexpr int D_MODEL = 1024;
constexpr int N_EXP  = 8;
constexpr int DFF    = 4096;
constexpr int CAP    = 1280;    // ceil(1.25*8192/8)

// ---------------- scratch (__device__ globals; alloc-free rule) ----------------
__device__ float  g_prob[T_TOK];
__device__ int    g_expert[T_TOK];
__device__ int    g_pos[T_TOK];
__device__ int    g_cnt[N_EXP];
__device__ int    g_tile[2];                 // persistent-GEMM work counters
__device__ int    g_slot2tok[N_EXP * CAP];
__device__ float  g_slot_prob[N_EXP * CAP];
__device__ __half g_disp[(size_t)N_EXP*CAP*D_MODEL];
__device__ __half g_w1[(size_t)N_EXP*DFF*D_MODEL];   // [e][dff][d]  K-major
__device__ __half g_w2[(size_t)N_EXP*D_MODEL*DFF];   // [e][d][dff]  K-major
__device__ __half g_h[(size_t)N_EXP*CAP*DFF];

// ---------------- helpers ----------------
static __device__ __forceinline__ uint32_t smem_u32(const void* p){
    uint32_t a;
    asm("{ .reg .u64 t; cvta.to.shared.u64 t, %1; cvt.u32.u64 %0, t; }" : "=r"(a) : "l"(p));
    return a;
}
static __device__ __forceinline__ void cp_async16(uint32_t s, const void* g){
    asm volatile("cp.async.cg.shared.global [%0], [%1], 16;" :: "r"(s), "l"(g) : "memory");
}
static __device__ __forceinline__ void cp_commit(){
    asm volatile("cp.async.commit_group;" ::: "memory");
}
template<int N>
static __device__ __forceinline__ void cp_wait(){
    asm volatile("cp.async.wait_group %0;" :: "n"(N) : "memory");
}
static __device__ __forceinline__ void ldmx4(uint32_t* r, uint32_t addr){
    asm volatile("ldmatrix.sync.aligned.m8n8.x4.shared.b16 {%0,%1,%2,%3}, [%4];"
                 : "=r"(r[0]), "=r"(r[1]), "=r"(r[2]), "=r"(r[3]) : "r"(addr));
}
static __device__ __forceinline__ void ldmx2(uint32_t* r, uint32_t addr){
    asm volatile("ldmatrix.sync.aligned.m8n8.x2.shared.b16 {%0,%1}, [%2];"
                 : "=r"(r[0]), "=r"(r[1]) : "r"(addr));
}
// fp16 operands, fp32 accumulator
static __device__ __forceinline__ void mma_f32(float* c, const uint32_t* a, const uint32_t* b){
    asm volatile(
        "mma.sync.aligned.m16n8k16.row.col.f32.f16.f16.f32 "
        "{%0,%1,%2,%3}, {%4,%5,%6,%7}, {%8,%9}, {%0,%1,%2,%3};"
        : "+f"(c[0]), "+f"(c[1]), "+f"(c[2]), "+f"(c[3])
        : "r"(a[0]), "r"(a[1]), "r"(a[2]), "r"(a[3]), "r"(b[0]), "r"(b[1]));
}

// ---------------- 1) gate: fp64-accum logits, softmax top-1 ----------------
__global__ void moe_gate(const float* __restrict__ tokens, const float* __restrict__ gw){
    __shared__ float s_gw[N_EXP * D_MODEL];  // 32 KB
    for (int i = threadIdx.x; i < N_EXP * D_MODEL; i += blockDim.x) s_gw[i] = gw[i];
    __syncthreads();
    int lane  = threadIdx.x & 31;
    int warp  = (blockIdx.x * blockDim.x + threadIdx.x) >> 5;
    int nwarp = (gridDim.x * blockDim.x) >> 5;
    for (int t = warp; t < T_TOK; t += nwarp){
        const float* tok = tokens + (size_t)t * D_MODEL;
        double acc[N_EXP];
        #pragma unroll
        for (int e = 0; e < N_EXP; e++) acc[e] = 0.0;
        for (int d = lane; d < D_MODEL; d += 32){
            double x = (double)tok[d];
            #pragma unroll
            for (int e = 0; e < N_EXP; e++) acc[e] += x * (double)s_gw[e * D_MODEL + d];
        }
        #pragma unroll
        for (int e = 0; e < N_EXP; e++){
            #pragma unroll
            for (int o = 16; o > 0; o >>= 1)
                acc[e] += __shfl_down_sync(0xffffffffu, acc[e], o);
        }
        if (lane == 0){
            int best = 0; double bv = acc[0];
            #pragma unroll
            for (int e = 1; e < N_EXP; e++) if (acc[e] > bv){ bv = acc[e]; best = e; }
            double s = 0.0;
            #pragma unroll
            for (int e = 0; e < N_EXP; e++) s += exp(acc[e] - bv);
            g_prob[t]   = (float)(1.0 / s);
            g_expert[t] = best;
        }
    }
}

// ---------------- 2) order-preserving per-expert rank scan + slot/counter init --------
__global__ void moe_scan(){
    __shared__ int s_base[N_EXP];
    __shared__ int s_wcnt[N_EXP][32];
    int tid = threadIdx.x, lane = tid & 31, w = tid >> 5;
    for (int i = tid; i < N_EXP * CAP; i += 1024) g_slot2tok[i] = -1;
    if (tid < 2) g_tile[tid] = 0;                    // reset persistent-GEMM counters
    if (tid < N_EXP) s_base[tid] = 0;
    for (int chunk = 0; chunk < T_TOK / 1024; chunk++){
        if (tid < N_EXP * 32) ((int*)s_wcnt)[tid] = 0;
        __syncthreads();
        int t = chunk * 1024 + tid;
        int e = g_expert[t];
        unsigned m = __match_any_sync(0xffffffffu, e);
        int rw = __popc(m & ((1u << lane) - 1u));
        if (rw == 0) s_wcnt[e][w] = __popc(m);
        __syncthreads();
        int base = s_base[e];
        for (int ww = 0; ww < w; ww++) base += s_wcnt[e][ww];
        int rank = base + rw;
        g_pos[t] = (rank < CAP) ? rank : -1;
        __syncthreads();
        if (tid < N_EXP){
            int s = 0;
            #pragma unroll
            for (int ww = 0; ww < 32; ww++) s += s_wcnt[tid][ww];
            s_base[tid] += s;
        }
        __syncthreads();
    }
    if (tid < N_EXP) g_cnt[tid] = (s_base[tid] < CAP) ? s_base[tid] : CAP;
}

// ---------------- 3) gather tokens -> dispatch (fp16) + slot maps + dropped-zero ------
__global__ void moe_gather(const float* __restrict__ tokens, float* __restrict__ out){
    int t = blockIdx.x;
    int pos = g_pos[t];
    if (pos < 0){
        float4* o = (float4*)(out + (size_t)t * D_MODEL);
        for (int i = threadIdx.x; i < D_MODEL / 4; i += blockDim.x)
            o[i] = make_float4(0.f, 0.f, 0.f, 0.f);
        return;
    }
    int e = g_expert[t];
    if (threadIdx.x == 0){
        g_slot2tok[e * CAP + pos]  = t;
        g_slot_prob[e * CAP + pos] = g_prob[t];
    }
    size_t dst = ((size_t)e * CAP + pos) * D_MODEL;
    const float4* src = (const float4*)(tokens + (size_t)t * D_MODEL);
    uint2* dh = (uint2*)(g_disp + dst);
    for (int i = threadIdx.x; i < D_MODEL / 4; i += blockDim.x){
        float4 v = src[i];
        __half2 h0 = __floats2half2_rn(v.x, v.y);
        __half2 h1 = __floats2half2_rn(v.z, v.w);
        uint2 H;
        H.x = *reinterpret_cast<unsigned*>(&h0);
        H.y = *reinterpret_cast<unsigned*>(&h1);
        dh[i] = H;
    }
}

// ---------------- 4) weight transpose (to K-major fp16), vectorized half2 stores ------
template<bool W1>
__global__ void moe_tw(const float* __restrict__ w){
    constexpr int R = W1 ? D_MODEL : DFF;   // rows of w  (= K of gemm)
    constexpr int C = W1 ? DFF : D_MODEL;   // cols of w  (= N of gemm)
    __half* oh = W1 ? g_w1 : g_w2;
    __shared__ float tile[64][33];
    int e = blockIdx.z;
    int c0 = blockIdx.x * 32, r0 = blockIdx.y * 64;
    const float* wp = w + (size_t)e * R * C;
    int x = threadIdx.x, y0 = threadIdx.y;    // blockDim (32, 8)
    #pragma unroll
    for (int yy = 0; yy < 64; yy += 8)
        tile[y0 + yy][x] = wp[(size_t)(r0 + y0 + yy) * C + c0 + x];
    __syncthreads();
    __half* poh = oh + (size_t)e * R * C;
    // store: each thread writes half2 covering rows (r0+2x, r0+2x+1) for 4 columns
    #pragma unroll
    for (int cc = 0; cc < 4; cc++){
        int c_loc = y0 * 4 + cc;
        __half2 hv = __floats2half2_rn(tile[2 * x][c_loc], tile[2 * x + 1][c_loc]);
        *(unsigned*)(poh + (size_t)(c0 + c_loc) * R + r0 + 2 * x) =
            *reinterpret_cast<unsigned*>(&hv);
    }
}

// ---------------- 5) persistent HMMA fp16 GEMM: BM=BN=128 BK=32, warp 64x64 -----------
constexpr int BM = 128, BN = 128, BK = 32;
constexpr int ROW_B   = 80;                      // padded row stride (64B data + 16B pad)
constexpr int OFF_A   = 0;
constexpr int OFF_B   = 128 * ROW_B;
constexpr int STAGE_B = 256 * ROW_B;             // 20480
constexpr int NSTAGE  = 4;
constexpr int GEMM_SMEM = NSTAGE * STAGE_B;      // 81920
constexpr int GEMM_THREADS = 128;                // 4 warps, 2x2 grid, warp tile 64x64
constexpr int GRID_PERSIST = 296;                // 2 CTAs/SM x 148 SMs

template<bool G1>
__global__ void __launch_bounds__(GEMM_THREADS, 2) moe_gemm(const float* __restrict__ bias,
                                                            float* __restrict__ out){
    constexpr int KTOT = G1 ? D_MODEL : DFF;
    constexpr int NTOT = G1 ? DFF : D_MODEL;
    constexpr int MT   = CAP / BM;               // 10
    constexpr int NT   = NTOT / BN;              // 32 (G1) / 8 (G2)
    constexpr int TOTAL = N_EXP * MT * NT;
    const __half* A = G1 ? g_disp : g_h;
    const __half* B = G1 ? g_w1 : g_w2;

    extern __shared__ char smem[];
    uint32_t sb = smem_u32(smem);
    __shared__ int s_tile;

    int tid  = threadIdx.x;
    int lane = tid & 31;
    int wid  = tid >> 5;
    int warpM = wid & 1;            // 2 x 2 warp grid; warp tile 64x64
    int warpN = wid >> 1;

    // static per-thread smem slots: idx = tid + i*128 (i<8); row = idx>>2, ch = idx&3
    uint32_t sptr[8];
    int srow[8], sch[8];
    #pragma unroll
    for (int i = 0; i < 8; i++){
        int idx = tid + i * GEMM_THREADS;
        srow[i] = idx >> 2; sch[i] = idx & 3;
        uint32_t so = (srow[i] < 128) ? (OFF_A + srow[i] * ROW_B)
                                      : (OFF_B + (srow[i] - 128) * ROW_B);
        sptr[i] = sb + so + sch[i] * 16;
    }
    uint32_t aoff = (uint32_t)((warpM * 64 + (lane & 7) + ((lane >> 3) & 1) * 8) * ROW_B
                    + ((lane >> 4) & 1) * 16);
    uint32_t boff = (uint32_t)((warpN * 64 + (lane & 7)) * ROW_B + ((lane >> 3) & 1) * 16);

    for (;;){
        if (tid == 0) s_tile = atomicAdd(&g_tile[G1 ? 0 : 1], 1);
        __syncthreads();                 // broadcast tile; also fences smem reuse
        int tile = s_tile;
        if (tile >= TOTAL) break;

        int e  = tile / (MT * NT);
        int r  = tile - e * (MT * NT);
        int n0 = (r / MT) * BN;          // m fastest: concurrent CTAs share B tile
        int m0 = (r % MT) * BM;
        if (m0 >= g_cnt[e]) continue;    // empty m-tile: steal next

        const __half* baseA = A + ((size_t)e * CAP  + m0) * KTOT;
        const __half* baseB = B + ((size_t)e * NTOT + n0) * KTOT;
        const __half* gptr[8];
        #pragma unroll
        for (int i = 0; i < 8; i++){
            const __half* gb = (srow[i] < 128) ? (baseA + (size_t)srow[i] * KTOT)
                                               : (baseB + (size_t)(srow[i] - 128) * KTOT);
            gptr[i] = gb + sch[i] * 8;
        }
        auto load_stage = [&](int kc, int stage){
            size_t koff = (size_t)kc * BK;
            uint32_t soff = stage * STAGE_B;
            #pragma unroll
            for (int i = 0; i < 8; i++)
                cp_async16(sptr[i] + soff, gptr[i] + koff);
        };

        constexpr int NK = KTOT / BK;
        #pragma unroll
        for (int s = 0; s < NSTAGE - 1; s++){ load_stage(s, s); cp_commit(); }

        float accF[4][8][4];
        #pragma unroll
        for (int mt = 0; mt < 4; mt++)
            #pragma unroll
            for (int nt = 0; nt < 8; nt++)
                #pragma unroll
                for (int c = 0; c < 4; c++) accF[mt][nt][c] = 0.f;

        int cur = 0, lds = NSTAGE - 1;
        #pragma unroll 1
        for (int kc = 0; kc < NK; kc++){
            cp_wait<NSTAGE - 2>();
            __syncthreads();
            int nx = kc + NSTAGE - 1;
            if (nx < NK) load_stage(nx, lds);
            cp_commit();

            uint32_t st = sb + cur * STAGE_B;
            uint32_t aH = st + OFF_A + aoff;
            uint32_t bH = st + OFF_B + boff;
            #pragma unroll
            for (int ks = 0; ks < 2; ks++){
                uint32_t bh[8][2];
                #pragma unroll
                for (int nt = 0; nt < 8; nt++)
                    ldmx2(bh[nt], bH + nt * 8 * ROW_B + ks * 32);
                #pragma unroll
                for (int mt = 0; mt < 4; mt++){
                    uint32_t ah[4];
                    ldmx4(ah, aH + mt * 16 * ROW_B + ks * 32);
                    #pragma unroll
                    for (int nt = 0; nt < 8; nt++)
                        mma_f32(accF[mt][nt], ah, bh[nt]);
                }
            }
            cur = (cur == NSTAGE - 1) ? 0 : cur + 1;
            lds = (lds == NSTAGE - 1) ? 0 : lds + 1;
        }

        // epilogue
        int rloc  = warpM * 64 + (lane >> 2);
        int cbase = n0 + warpN * 64 + 2 * (lane & 3);
        const float* bptr = bias + (size_t)e * NTOT;
        #pragma unroll
        for (int mt = 0; mt < 4; mt++){
            #pragma unroll
            for (int h = 0; h < 2; h++){
                int slot = m0 + rloc + mt * 16 + h * 8;
                int t = 0; float p = 0.f; float* op = nullptr;
                if constexpr (!G1){
                    t = g_slot2tok[e * CAP + slot];
                    if (t < 0) continue;
                    p = g_slot_prob[e * CAP + slot];
                    op = out + (size_t)t * D_MODEL;
                }
                size_t row = (size_t)e * CAP + slot;
                #pragma unroll
                for (int nt = 0; nt < 8; nt++){
                    int n = cbase + nt * 8;
                    float v0 = accF[mt][nt][h*2+0] + __ldg(bptr + n);
                    float v1 = accF[mt][nt][h*2+1] + __ldg(bptr + n + 1);
                    if constexpr (G1){
                        v0 = fmaxf(v0, 0.f); v1 = fmaxf(v1, 0.f);
                        __half2 hv = __floats2half2_rn(v0, v1);
                        *(unsigned*)(g_h + row * DFF + n) = *reinterpret_cast<unsigned*>(&hv);
                    } else {
                        float2 v = make_float2(v0 * p, v1 * p);
                        *(float2*)(op + n) = v;
                    }
                }
            }
        }
    }
}

// ---------------- launch ----------------
extern "C" void kernel_launch(void* const* d_in, const int* in_sizes, int n_in,
                              void* d_out, int out_size){
    const float* inputs = (const float*)d_in[0];
    const float* gate_w = (const float*)d_in[1];
    const float* w1     = (const float*)d_in[2];
    const float* b1     = (const float*)d_in[3];
    const float* w2     = (const float*)d_in[4];
    const float* b2     = (const float*)d_in[5];
    float* out = (float*)d_out;

    cudaFuncSetAttribute(moe_gemm<true>,  cudaFuncAttributeMaxDynamicSharedMemorySize, GEMM_SMEM);
    cudaFuncSetAttribute(moe_gemm<false>, cudaFuncAttributeMaxDynamicSharedMemorySize, GEMM_SMEM);

    moe_gate<<<128, 256>>>(inputs, gate_w);                                          // 1
    moe_scan<<<1, 1024>>>();                                                         // 2
    moe_gather<<<T_TOK, 128>>>(inputs, out);                                         // 3
    moe_tw<true ><<<dim3(DFF / 32,     D_MODEL / 64, N_EXP), dim3(32, 8)>>>(w1);     // 4
    moe_tw<false><<<dim3(D_MODEL / 32, DFF / 64,     N_EXP), dim3(32, 8)>>>(w2);     // 5
    moe_gemm<true ><<<GRID_PERSIST, GEMM_THREADS, GEMM_SMEM>>>(b1, nullptr);         // 6
    moe_gemm<false><<<GRID_PERSIST, GEMM_THREADS, GEMM_SMEM>>>(b2, out);             // 7
}